// round 17
// baseline (speedup 1.0000x reference)
#include <cuda_runtime.h>
#include <cuda_bf16.h>

// src [8,16,512,512] f32, flow [8,2,512,512] f32, out [8,16,512,512] f32.
//
// Index math reproduces XLA's lowering bit-exactly (reciprocal-constant rewrite
// of /511, fp32-rounded intermediates, no FMA contraction, rint half-to-even,
// border clamp). Verified rel_err == 0.0 in R3-R16.
//
// R17 = R13 (32x16 tile, 512 thr, 1 px/thread, 64 warps/SM) with ONE change:
// within-warp lane shape 32(x)x1(h) -> 16(x)x2(h). A warp-gather's footprint
// shrinks from ~160B x-span per touched row (~2.5 lines) to ~96B (~1.3 lines),
// cutting L1tex wavefronts/gather ~35% at the cost of +1 store wavefront.
// Warps tile the 32x16 CTA as 2(x) x 8(h) patches.

#define B 8
#define C 16
#define H 512
#define W 512
#define HW (H * W)          // 1<<18
#define W_BITS 9

#define TILE_X 32
#define TILE_H 16
#define TPB (TILE_X * TILE_H)   // 512
#define XT (W / TILE_X)     // 16 x-tiles
#define HT (H / TILE_H)     // 32 h-tiles

__device__ __forceinline__ int ref_index(float coord, float disp)
{
    const float rcp = 1.0f / 511.0f;         // fp32(1/511), XLA recip rewrite
    float t = __fadd_rn(coord, disp);        // ii + flow
    t = __fmul_rn(t, rcp);                   // * (1/511)
    t = __fadd_rn(t, -0.5f);                 // - 0.5
    t = __fmul_rn(2.0f, t);                  // * 2 (exact)
    t = __fadd_rn(t, 1.0f);                  // + 1
    t = __fmul_rn(t, 0.5f);                  // * 0.5 (exact)
    t = __fmul_rn(t, 511.0f);                // * 511
    int i = __float2int_rn(t);               // round half-to-even
    return min(max(i, 0), 511);              // border clamp
}

__global__ __launch_bounds__(TPB, 4) void flow_warp_w16x2_kernel(
    const float* __restrict__ src,
    const float* __restrict__ flow,
    float* __restrict__ out)
{
    int bidx = blockIdx.x;
    int xt = bidx & (XT - 1);               // x-tile
    int ht = (bidx >> 4) & (HT - 1);        // h-tile
    int b  = bidx >> 9;                     // batch

    int lane = threadIdx.x & 31;
    int wrp  = threadIdx.x >> 5;            // 0..15

    // warp grid inside tile: 2 (x) x 8 (h); lane patch: 16 (x) x 2 (h)
    int wx = wrp & 1;                       // warp x-half
    int wh = wrp >> 1;                      // warp h-pair
    int lx = lane & 15;
    int lh = lane >> 4;

    int h  = ht * TILE_H + wh * 2 + lh;
    int w  = xt * TILE_X + wx * 16 + lx;
    int hw = (h << W_BITS) + w;

    const float* fb = flow + (size_t)b * 2 * HW;
    float f0 = __ldcs(fb + hw);             // row displacement (streamed)
    float f1 = __ldcs(fb + HW + hw);        // col displacement (streamed)

    int yi = ref_index((float)h, f0);
    int xi = ref_index((float)w, f1);
    int lin = (yi << W_BITS) + xi;

    const float* sb = src + (size_t)b * C * HW;
    float*       ob = out + (size_t)b * C * HW;

    #pragma unroll
    for (int c = 0; c < C; ++c) {
        __stcs(ob + c * HW + hw, __ldg(sb + c * HW + lin));
    }
}

extern "C" void kernel_launch(void* const* d_in, const int* in_sizes, int n_in,
                              void* d_out, int out_size)
{
    const float* src  = (const float*)d_in[0];
    const float* flow = (const float*)d_in[1];
    float*       out  = (float*)d_out;

    int blocks = B * HT * XT;              // 4096
    flow_warp_w16x2_kernel<<<blocks, TPB>>>(src, flow, out);
}